// round 15
// baseline (speedup 1.0000x reference)
#include <cuda_runtime.h>
#include <cuda_fp16.h>
#include <cuda_bf16.h>
#include <math.h>
#include <stdint.h>

__device__ float          g_bufA[128000000];
__device__ float          g_bufB[16000000];
__device__ __nv_bfloat16  g_xt[384000000];    // reused as __half planes
__device__ __nv_bfloat16  g_ws[43300000];     // reused as __half split weights
__device__ float          g_mean[512];
__device__ float          g_istd[512];
__device__ float          g_cnorm[1024];
__device__ int            g_idx[8192];

__device__ __forceinline__ float gelu_f(float x) {
    return 0.5f * x * (1.0f + erff(x * 0.7071067811865476f));
}
__device__ __forceinline__ uint32_t smem_u32(const void* p) {
    uint32_t a;
    asm("{ .reg .u64 t; cvta.to.shared.u64 t, %1; cvt.u32.u64 %0, t; }" : "=r"(a) : "l"(p));
    return a;
}
__device__ __forceinline__ void cpa16(uint32_t dst, const void* src) {
    asm volatile("cp.async.cg.shared.global [%0], [%1], 16;" :: "r"(dst), "l"(src));
}
__device__ __forceinline__ void cpa16z(uint32_t dst, const void* src, uint32_t sz) {
    asm volatile("cp.async.cg.shared.global [%0], [%1], 16, %2;" :: "r"(dst), "l"(src), "r"(sz));
}
__device__ __forceinline__ void ldmx4(uint32_t a, uint32_t* r) {
    asm volatile("ldmatrix.sync.aligned.m8n8.x4.shared.b16 {%0,%1,%2,%3}, [%4];"
                 : "=r"(r[0]), "=r"(r[1]), "=r"(r[2]), "=r"(r[3]) : "r"(a));
}
__device__ __forceinline__ void mma16816(float* c, const uint32_t* a, uint32_t b0, uint32_t b1) {
    asm volatile("mma.sync.aligned.m16n8k16.row.col.f32.f16.f16.f32 "
                 "{%0,%1,%2,%3}, {%4,%5,%6,%7}, {%8,%9}, {%0,%1,%2,%3};"
                 : "+f"(c[0]), "+f"(c[1]), "+f"(c[2]), "+f"(c[3])
                 : "r"(a[0]), "r"(a[1]), "r"(a[2]), "r"(a[3]), "r"(b0), "r"(b1));
}

struct f32x2 { unsigned long long u; };
__device__ __forceinline__ f32x2 pack2(float lo, float hi) {
    f32x2 r; asm("mov.b64 %0, {%1, %2};" : "=l"(r.u) : "f"(lo), "f"(hi)); return r;
}
__device__ __forceinline__ void fma2(f32x2 &d, f32x2 a, f32x2 b) {
    asm("fma.rn.f32x2 %0, %1, %2, %0;" : "+l"(d.u) : "l"(a.u), "l"(b.u));
}
__device__ __forceinline__ void unpack2(f32x2 v, float &lo, float &hi) {
    asm("mov.b64 {%0, %1}, %2;" : "=f"(lo), "=f"(hi) : "l"(v.u));
}

// conv0: Cin=1 -> yT[b][l][256]
__global__ __launch_bounds__(256)
void conv0_t(const float* __restrict__ x, const float* __restrict__ w,
             const float* __restrict__ bias, float* __restrict__ yT, int Lin, int Lout)
{
    __shared__ float Wsh[2560];
    __shared__ float Xsh[85];
    int b = blockIdx.y, l0 = blockIdx.x * 16, co = threadIdx.x;
    for (int i = co; i < 2560; i += 256) Wsh[i] = w[i];
    int g0 = 5 * l0 - 5;
    for (int i = co; i < 85; i += 256) {
        int gl = g0 + i;
        Xsh[i] = (gl >= 0 && gl < Lin) ? x[(size_t)b * Lin + gl] : 0.0f;
    }
    __syncthreads();
    float wr[10];
    #pragma unroll
    for (int t = 0; t < 10; t++) wr[t] = Wsh[co * 10 + t];
    float bv = bias[co];
    for (int j = 0; j < 16; j++) {
        int l = l0 + j;
        if (l >= Lout) break;
        float a = bv;
        #pragma unroll
        for (int t = 0; t < 10; t++) a = fmaf(wr[t], Xsh[5 * j + t], a);
        yT[((size_t)b * Lout + l) * 256 + co] = a;
    }
}

// All 6 layers' weights -> fp16 2-comp split SCALED BY 16, layout [comp][co][t][ci]
__global__ __launch_bounds__(256)
void wprep_all(const float* __restrict__ w1, const float* __restrict__ wr,
               __half* __restrict__ d)
{
    int L = blockIdx.y, co = blockIdx.x;
    int Cin = (L == 0) ? 256 : 512;
    const float* src = (L == 0) ? w1 : wr + (size_t)(L - 1) * 512 * 512 * 10;
    __half* dst = (L == 0) ? d : d + 2621440 + (size_t)(L - 1) * 5242880;
    size_t cs = (size_t)512 * 10 * Cin;
    for (int i = threadIdx.x; i < Cin * 10; i += 256) {
        int ci = i / 10, t = i - ci * 10;
        float v = 16.0f * src[((size_t)co * Cin + ci) * 10 + t];
        __half c0 = __float2half(v);
        __half c1 = __float2half(v - __half2float(c0));
        size_t o = ((size_t)co * 10 + t) * Cin + ci;
        dst[o] = c0; dst[cs + o] = c1;
    }
}

// ---------------------------------------------------------------------------
// mma.sync fp16 conv. CTA 256thr/8 warps; tile M=128(l) x N=128(co);
// warp 32x64 (4x2 warp grid). K-chunk = 64 ci per tap (4 k16 steps).
// Weights pre-scaled x16; activations split unscaled -> all 3 products share
// ONE fp32 accumulator set; drain g = fma(c, 1/16, g) every 4 chunks.
// 3-stage cp.async pipeline; incremental +64-half pointers (interior CTAs).
// ---------------------------------------------------------------------------
#define ROWB   144            // 128B data + 16B pad
#define CMPB   18432          // 128 rows * 144B (per comp, A or B)
#define AHALF  36864          // 2 A comps
#define BUFB   73728          // A(2) + B(2)
#define NSTG   3

template<int CIN>
__global__ __launch_bounds__(256, 1)
void conv_mma(const __half* __restrict__ xs, size_t planeStride,
              const __half* __restrict__ ws, size_t wcs,
              const float* __restrict__ bias, float* __restrict__ yT,
              int Cout, int Lin, int Lout)
{
    extern __shared__ __align__(128) char smem[];
    uint32_t sbase = smem_u32(smem);
    int tid = threadIdx.x, wid = tid >> 5, lane = tid & 31;
    int wm = wid & 3, wn = wid >> 2;          // 4 x 2 warp grid
    int co0 = blockIdx.x * 128;
    int l0  = blockIdx.y * 128;
    int b   = blockIdx.z;

    const __half* xb = xs + (size_t)b * (size_t)Lin * CIN;
    constexpr int NKB = (CIN == 256) ? 2 : 3;   // log2(chunks of 64 per tap)
    constexpr int NKC = 1 << NKB;
    constexpr int NC  = 10 * NKC;

    float c[2][8][4];     // working fp32 accumulators (single set)
    float g[2][8][4];     // grand accumulators (true scale)
    #pragma unroll
    for (int i = 0; i < 2; i++)
        #pragma unroll
        for (int j = 0; j < 8; j++)
            #pragma unroll
            for (int q = 0; q < 4; q++) { c[i][j][q] = 0.0f; g[i][j][q] = 0.0f; }

    int rowX = tid & 127, half = tid >> 7;      // loader mapping (fixed/thread)
    uint32_t smoff = (uint32_t)(rowX * ROWB + half * 64);

    #define COMPUTE(kk) do {                                                          \
        int _kc = (kk);                                                               \
        uint32_t Ab = sbase + (uint32_t)(_kc % NSTG) * BUFB;                          \
        uint32_t Bb = Ab + AHALF;                                                     \
        uint32_t aw = Ab + (wm * 32 + (lane & 15)) * ROWB + (lane >> 4) * 16;         \
        uint32_t bw = Bb + (wn * 64 + ((lane >> 4) << 3) + (lane & 7)) * ROWB         \
                        + ((lane >> 3) & 1) * 16;                                     \
        _Pragma("unroll")                                                             \
        for (int ks = 0; ks < 4; ks++) {                                              \
            uint32_t a[2][2][4], bf[2][4][4];                                         \
            _Pragma("unroll")                                                         \
            for (int cp = 0; cp < 2; cp++)                                            \
                _Pragma("unroll")                                                     \
                for (int mt = 0; mt < 2; mt++)                                        \
                    ldmx4(aw + cp * CMPB + mt * (16 * ROWB) + ks * 32, a[cp][mt]);    \
            _Pragma("unroll")                                                         \
            for (int cp = 0; cp < 2; cp++)                                            \
                _Pragma("unroll")                                                     \
                for (int n2 = 0; n2 < 4; n2++)                                        \
                    ldmx4(bw + cp * CMPB + n2 * (16 * ROWB) + ks * 32, bf[cp][n2]);   \
            _Pragma("unroll")                                                         \
            for (int mt = 0; mt < 2; mt++)                                            \
                _Pragma("unroll")                                                     \
                for (int nt = 0; nt < 8; nt++) {                                      \
                    int n2 = nt >> 1, i0 = (nt & 1) * 2;                              \
                    uint32_t b0a = bf[0][n2][i0], b0b = bf[0][n2][i0 + 1];            \
                    uint32_t b1a = bf[1][n2][i0], b1b = bf[1][n2][i0 + 1];            \
                    mma16816(c[mt][nt], a[0][mt], b0a, b0b);                          \
                    mma16816(c[mt][nt], a[0][mt], b1a, b1b);                          \
                    mma16816(c[mt][nt], a[1][mt], b0a, b0b);                          \
                }                                                                     \
        }                                                                             \
        if ((_kc & 3) == 3 || _kc == NC - 1) {                                        \
            _Pragma("unroll")                                                         \
            for (int mt = 0; mt < 2; mt++)                                            \
                _Pragma("unroll")                                                     \
                for (int nt = 0; nt < 8; nt++)                                        \
                    _Pragma("unroll")                                                 \
                    for (int q = 0; q < 4; q++) {                                     \
                        g[mt][nt][q] = fmaf(c[mt][nt][q], 0.0625f, g[mt][nt][q]);     \
                        c[mt][nt][q] = 0.0f;                                          \
                    }                                                                 \
        }                                                                             \
        __syncthreads();                                                              \
    } while (0)

    bool interior = (l0 >= 3) && (2 * l0 + 260 < Lin);

    if (interior) {
        const __half* pA = xb + (size_t)(2 * l0 - 5 + 2 * rowX) * CIN + half * 32;
        const __half* pB = ws + ((size_t)(co0 + rowX) * 10) * CIN + half * 32;
        int fsi = 0;
        #define ISSUE_F() do {                                                        \
            uint32_t Ab = sbase + (uint32_t)(fsi % NSTG) * BUFB + smoff;              \
            uint32_t Bb = Ab + AHALF;                                                 \
            _Pragma("unroll")                                                         \
            for (int cp = 0; cp < 2; cp++)                                            \
                _Pragma("unroll")                                                     \
                for (int sg = 0; sg < 4; sg++)                                        \
                    cpa16(Ab + cp * CMPB + sg * 16,                                   \
                          pA + (size_t)cp * planeStride + sg * 8);                    \
            _Pragma("unroll")                                                         \
            for (int cp = 0; cp < 2; cp++)                                            \
                _Pragma("unroll")                                                     \
                for (int sg = 0; sg < 4; sg++)                                        \
                    cpa16(Bb + cp * CMPB + sg * 16,                                   \
                          pB + (size_t)cp * wcs + sg * 8);                            \
            asm volatile("cp.async.commit_group;" ::: "memory");                      \
            pA += 64; pB += 64; fsi++;                                                \
        } while (0)
        ISSUE_F();
        ISSUE_F();
        for (int k = 0; k < NC; k++) {
            if (k + 2 < NC) {
                ISSUE_F();
                asm volatile("cp.async.wait_group 2;" ::: "memory");
            } else if (k + 1 < NC) {
                asm volatile("cp.async.wait_group 1;" ::: "memory");
            } else {
                asm volatile("cp.async.wait_group 0;" ::: "memory");
            }
            __syncthreads();
            COMPUTE(k);
        }
    } else {
        #define ISSUE_S(kk) do {                                                      \
            int _k = (kk);                                                            \
            int _t = _k >> NKB, _ci0 = (_k & (NKC - 1)) << 6;                         \
            uint32_t Ab = sbase + (uint32_t)(_k % NSTG) * BUFB + smoff;               \
            uint32_t Bb = Ab + AHALF;                                                 \
            int r = 2 * l0 - 5 + _t + 2 * rowX;                                       \
            int ok = (r >= 0 && r < Lin);                                             \
            const __half* sa = xb + (size_t)(ok ? r : 0) * CIN + _ci0 + half * 32;    \
            const __half* sb2 = ws + ((size_t)(co0 + rowX) * 10 + _t) * CIN           \
                              + _ci0 + half * 32;                                     \
            _Pragma("unroll")                                                         \
            for (int cp = 0; cp < 2; cp++)                                            \
                _Pragma("unroll")                                                     \
                for (int sg = 0; sg < 4; sg++)                                        \
                    cpa16z(Ab + cp * CMPB + sg * 16,                                  \
                           sa + (size_t)cp * planeStride + sg * 8, ok ? 16u : 0u);    \
            _Pragma("unroll")                                                         \
            for (int cp = 0; cp < 2; cp++)                                            \
                _Pragma("unroll")                                                     \
                for (int sg = 0; sg < 4; sg++)                                        \
                    cpa16(Bb + cp * CMPB + sg * 16,                                   \
                          sb2 + (size_t)cp * wcs + sg * 8);                           \
            asm volatile("cp.async.commit_group;" ::: "memory");                      \
        } while (0)
        ISSUE_S(0);
        ISSUE_S(1);
        for (int k = 0; k < NC; k++) {
            if (k + 2 < NC) {
                ISSUE_S(k + 2);
                asm volatile("cp.async.wait_group 2;" ::: "memory");
            } else if (k + 1 < NC) {
                asm volatile("cp.async.wait_group 1;" ::: "memory");
            } else {
                asm volatile("cp.async.wait_group 0;" ::: "memory");
            }
            __syncthreads();
            COMPUTE(k);
        }
    }

    #pragma unroll
    for (int mt = 0; mt < 2; mt++) {
        int lr = l0 + wm * 32 + mt * 16 + (lane >> 2);
        #pragma unroll
        for (int nt = 0; nt < 8; nt++) {
            int col = co0 + wn * 64 + nt * 8 + (lane & 3) * 2;
            float b0 = bias[col], b1 = bias[col + 1];
            if (lr < Lout) {
                float2 v = make_float2(g[mt][nt][0] + b0, g[mt][nt][1] + b1);
                *(float2*)&yT[((size_t)b * Lout + lr) * Cout + col] = v;
            }
            if (lr + 8 < Lout) {
                float2 v = make_float2(g[mt][nt][2] + b0, g[mt][nt][3] + b1);
                *(float2*)&yT[((size_t)b * Lout + lr + 8) * Cout + col] = v;
            }
        }
    }
}

// GN stats over [b][l][C]
__global__ __launch_bounds__(256)
void gn_stats_t(const float* __restrict__ x, float* __restrict__ mean,
                float* __restrict__ istd, int L, int C, int G)
{
    int blk = blockIdx.x, b = blk / G, g = blk % G;
    const float* p = x + (size_t)b * L * C + g * 16;
    float s = 0.0f, s2 = 0.0f;
    int tot = L * 16;
    for (int i = threadIdx.x; i < tot; i += 256) {
        int l = i >> 4, cc = i & 15;
        float v = p[(size_t)l * C + cc];
        s += v; s2 = fmaf(v, v, s2);
    }
    __shared__ float sa[256], sbm[256];
    int tid = threadIdx.x;
    sa[tid] = s; sbm[tid] = s2;
    __syncthreads();
    for (int o = 128; o > 0; o >>= 1) {
        if (tid < o) { sa[tid] += sa[tid + o]; sbm[tid] += sbm[tid + o]; }
        __syncthreads();
    }
    if (tid == 0) {
        float m = sa[0] / (float)tot;
        float var = sbm[0] / (float)tot - m * m;
        mean[blk] = m;
        istd[blk] = rsqrtf(var + 1e-5f);
    }
}

// GN apply + GELU + unscaled fp16 2-way split -> planes
__global__ __launch_bounds__(256)
void ng_split(const float* __restrict__ x, const float* __restrict__ mean,
              const float* __restrict__ istd, const float* __restrict__ gma,
              const float* __restrict__ bta, __half* __restrict__ xs,
              size_t ps, int L, int C, int G)
{
    int b = blockIdx.y;
    size_t i4 = (size_t)blockIdx.x * 256 + threadIdx.x;
    size_t n4 = (size_t)L * C >> 2;
    if (i4 >= n4) return;
    size_t base = (size_t)b * L * C;
    float4 v = ((const float4*)(x + base))[i4];
    int cc = (int)((i4 << 2) % (size_t)C);
    int bg = b * G + (cc >> 4);
    float mu = mean[bg], is = istd[bg];
    float o[4] = {v.x, v.y, v.z, v.w};
    __half p0[4], p1[4];
    #pragma unroll
    for (int j = 0; j < 4; j++) {
        float h = gelu_f((o[j] - mu) * is * gma[cc + j] + bta[cc + j]);
        __half a = __float2half(h);
        p0[j] = a;
        p1[j] = __float2half(h - __half2float(a));
    }
    ((uint64_t*)(xs + base))[i4]      = *(uint64_t*)p0;
    ((uint64_t*)(xs + ps + base))[i4] = *(uint64_t*)p1;
}

__global__ __launch_bounds__(256)
void ng_inplace(float* __restrict__ x, const float* __restrict__ mean,
                const float* __restrict__ istd, const float* __restrict__ gma,
                const float* __restrict__ bta, int L, int C, int G)
{
    int b = blockIdx.y;
    size_t i4 = (size_t)blockIdx.x * 256 + threadIdx.x;
    size_t n4 = (size_t)L * C >> 2;
    if (i4 >= n4) return;
    size_t base = (size_t)b * L * C;
    float4 v = ((const float4*)(x + base))[i4];
    int cc = (int)((i4 << 2) % (size_t)C);
    int bg = b * G + (cc >> 4);
    float mu = mean[bg], is = istd[bg];
    v.x = gelu_f((v.x - mu) * is * gma[cc + 0] + bta[cc + 0]);
    v.y = gelu_f((v.y - mu) * is * gma[cc + 1] + bta[cc + 1]);
    v.z = gelu_f((v.z - mu) * is * gma[cc + 2] + bta[cc + 2]);
    v.w = gelu_f((v.w - mu) * is * gma[cc + 3] + bta[cc + 3]);
    ((float4*)(x + base))[i4] = v;
}

// SIMT f32x2 GEMM tail
__global__ __launch_bounds__(128)
void gemm_nt(const float* __restrict__ A, const float* __restrict__ B,
             const float* __restrict__ bias, float* __restrict__ out, int K, int Nj)
{
    __shared__ float As[64][17], Bs[64][17];
    int tid = threadIdx.x;
    int i0 = blockIdx.y * 64, j0 = blockIdx.x * 64;
    int isub = tid >> 4, jsub = tid & 15;
    f32x2 acc[8][2];
    #pragma unroll
    for (int i = 0; i < 8; i++) { acc[i][0].u = 0ull; acc[i][1].u = 0ull; }
    for (int k0 = 0; k0 < K; k0 += 16) {
        __syncthreads();
        for (int x = tid; x < 1024; x += 128) {
            int r = x >> 4, cc = x & 15;
            As[r][cc] = A[(size_t)(i0 + r) * K + k0 + cc];
            Bs[r][cc] = B[(size_t)(j0 + r) * K + k0 + cc];
        }
        __syncthreads();
        #pragma unroll 4
        for (int k = 0; k < 16; k++) {
            f32x2 b0 = pack2(Bs[jsub * 4 + 0][k], Bs[jsub * 4 + 1][k]);
            f32x2 b1 = pack2(Bs[jsub * 4 + 2][k], Bs[jsub * 4 + 3][k]);
            #pragma unroll
            for (int ii = 0; ii < 8; ii++) {
                float a = As[isub + (ii << 3)][k];
                f32x2 a2 = pack2(a, a);
                fma2(acc[ii][0], a2, b0);
                fma2(acc[ii][1], a2, b1);
            }
        }
    }
    int j = j0 + jsub * 4;
    float bv0 = bias ? bias[j] : 0.0f, bv1 = bias ? bias[j + 1] : 0.0f;
    float bv2 = bias ? bias[j + 2] : 0.0f, bv3 = bias ? bias[j + 3] : 0.0f;
    #pragma unroll
    for (int ii = 0; ii < 8; ii++) {
        int i = i0 + isub + (ii << 3);
        float o0, o1, o2, o3;
        unpack2(acc[ii][0], o0, o1);
        unpack2(acc[ii][1], o2, o3);
        float* p = out + (size_t)i * Nj + j;
        p[0] = o0 + bv0; p[1] = o1 + bv1; p[2] = o2 + bv2; p[3] = o3 + bv3;
    }
}

__global__ __launch_bounds__(256)
void cb_norms(const float* __restrict__ cbk, float* __restrict__ cn)
{
    const float4* row = (const float4*)(cbk + (size_t)blockIdx.x * 1536);
    float s = 0.0f;
    for (int i = threadIdx.x; i < 384; i += 256) {
        float4 v = row[i];
        s += v.x * v.x + v.y * v.y + v.z * v.z + v.w * v.w;
    }
    __shared__ float sa[256];
    int tid = threadIdx.x;
    sa[tid] = s;
    __syncthreads();
    for (int o = 128; o > 0; o >>= 1) {
        if (tid < o) sa[tid] += sa[tid + o];
        __syncthreads();
    }
    if (tid == 0) cn[blockIdx.x] = sa[0];
}

__global__ __launch_bounds__(256)
void vq_argmin(const float* __restrict__ sc, const float* __restrict__ cn,
               int* __restrict__ idx, int NS)
{
    int g = blockIdx.x * 8 + (threadIdx.x >> 5);
    int lane = threadIdx.x & 31;
    if (g >= NS) return;
    const float* s = sc + (size_t)g * 1024;
    float best = 3.4e38f; int bi = 1 << 30;
    for (int j = lane; j < 1024; j += 32) {
        float d = fmaf(-2.0f, s[j], cn[j]);
        if (d < best) { best = d; bi = j; }
    }
    #pragma unroll
    for (int o = 16; o > 0; o >>= 1) {
        float ov = __shfl_xor_sync(0xffffffffu, best, o);
        int   oi = __shfl_xor_sync(0xffffffffu, bi,   o);
        if (ov < best || (ov == best && oi < bi)) { best = ov; bi = oi; }
    }
    if (lane == 0) idx[g] = bi;
}

__global__ __launch_bounds__(256)
void final_ln(const float* __restrict__ cbk, const int* __restrict__ idx,
              const float* __restrict__ pos, const float* __restrict__ mod,
              const float* __restrict__ lng, const float* __restrict__ lnb,
              float* __restrict__ out, int S, int NS)
{
    int n = blockIdx.x, s = n % S, tid = threadIdx.x;
    __shared__ float row[1536];
    __shared__ float sa[256], sbm[256];
    const float* c = cbk + (size_t)idx[n] * 1536;
    const float* p = pos + (size_t)s * 1536;
    float ls = 0.0f, ls2 = 0.0f;
    for (int e = tid; e < 1536; e += 256) {
        float v = c[e] + p[e] + mod[e];
        row[e] = v;
        ls += v; ls2 = fmaf(v, v, ls2);
    }
    sa[tid] = ls; sbm[tid] = ls2;
    __syncthreads();
    for (int o = 128; o > 0; o >>= 1) {
        if (tid < o) { sa[tid] += sa[tid + o]; sbm[tid] += sbm[tid + o]; }
        __syncthreads();
    }
    float m = sa[0] * (1.0f / 1536.0f);
    float var = sbm[0] * (1.0f / 1536.0f) - m * m;
    float r = rsqrtf(var + 1e-5f);
    for (int e = tid; e < 1536; e += 256)
        out[(size_t)n * 1536 + e] = (row[e] - m) * r * lng[e] + lnb[e];
    if (tid == 0) {
        out[(size_t)NS * 1536 + n]      = 1.0f;
        out[(size_t)NS * 1536 + NS + n] = (float)idx[n];
    }
}

extern "C" void kernel_launch(void* const* d_in, const int* in_sizes, int n_in,
                              void* d_out, int out_size)
{
    const float* wav = (const float*)d_in[0];
    const float* w0  = (const float*)d_in[1];
    const float* b0  = (const float*)d_in[2];
    const float* w1  = (const float*)d_in[3];
    const float* b1  = (const float*)d_in[4];
    const float* wr  = (const float*)d_in[5];
    const float* br  = (const float*)d_in[6];
    const float* g0  = (const float*)d_in[7];
    const float* bb0 = (const float*)d_in[8];
    const float* gr  = (const float*)d_in[9];
    const float* brr = (const float*)d_in[10];
    const float* pw  = (const float*)d_in[11];
    const float* pb  = (const float*)d_in[12];
    const float* cbk = (const float*)d_in[13];
    const float* pos = (const float*)d_in[14];
    const float* mod = (const float*)d_in[15];
    const float* lng = (const float*)d_in[16];
    const float* lnb = (const float*)d_in[17];
    float* out = (float*)d_out;

    const int B = 8;
    int Lw = in_sizes[0] / B;
    int L[7];
    L[0] = Lw / 5 + 1;
    for (int i = 1; i <= 6; i++) L[i] = L[i - 1] / 2 + 1;

    float *bufA, *bufB, *mean_, *istd_, *cn_;
    __half *xt_, *ws_;
    int *idx_;
    cudaGetSymbolAddress((void**)&bufA,  g_bufA);
    cudaGetSymbolAddress((void**)&bufB,  g_bufB);
    cudaGetSymbolAddress((void**)&xt_,   g_xt);
    cudaGetSymbolAddress((void**)&ws_,   g_ws);
    cudaGetSymbolAddress((void**)&mean_, g_mean);
    cudaGetSymbolAddress((void**)&istd_, g_istd);
    cudaGetSymbolAddress((void**)&cn_,   g_cnorm);
    cudaGetSymbolAddress((void**)&idx_,  g_idx);

    const int SMEMSZ = NSTG * BUFB;   // 221184
    cudaFuncSetAttribute(conv_mma<256>, cudaFuncAttributeMaxDynamicSharedMemorySize, SMEMSZ);
    cudaFuncSetAttribute(conv_mma<512>, cudaFuncAttributeMaxDynamicSharedMemorySize, SMEMSZ);

    cb_norms<<<1024, 256>>>(cbk, cn_);
    wprep_all<<<dim3(512, 6), 256>>>(w1, wr, ws_);

    conv0_t<<<dim3((L[0] + 15) / 16, B), 256>>>(wav, w0, b0, bufA, Lw, L[0]);
    gn_stats_t<<<B * 16, 256>>>(bufA, mean_, istd_, L[0], 256, 16);
    {
        size_t ps = (size_t)B * L[0] * 256;
        int nb = (int)(((size_t)L[0] * 256 / 4 + 255) / 256);
        ng_split<<<dim3(nb, B), 256>>>(bufA, mean_, istd_, g0, bb0, xt_, ps, L[0], 256, 16);
    }

    // layer 1 (MMA, Cin=256)
    conv_mma<256><<<dim3(4, (L[1] + 127) / 128, B), 256, SMEMSZ>>>(
        xt_, (size_t)B * L[0] * 256, ws_, 1310720, b1, bufA, 512, L[0], L[1]);
    gn_stats_t<<<B * 32, 256>>>(bufA, mean_, istd_, L[1], 512, 32);
    {
        size_t ps = (size_t)B * L[1] * 512;
        int nb = (int)(((size_t)L[1] * 512 / 4 + 255) / 256);
        ng_split<<<dim3(nb, B), 256>>>(bufA, mean_, istd_, gr, brr, xt_, ps, L[1], 512, 32);
    }

    // layers 2..6 (MMA, Cin=512)
    for (int i = 0; i < 5; i++) {
        int Lin = L[1 + i], Lo = L[2 + i];
        conv_mma<512><<<dim3(4, (Lo + 127) / 128, B), 256, SMEMSZ>>>(
            xt_, (size_t)B * Lin * 512, ws_ + 2621440 + (size_t)i * 5242880, 2621440,
            br + i * 512, bufA, 512, Lin, Lo);
        gn_stats_t<<<B * 32, 256>>>(bufA, mean_, istd_, Lo, 512, 32);
        int nb = (int)(((size_t)Lo * 512 / 4 + 255) / 256);
        if (i < 4) {
            size_t ps = (size_t)B * Lo * 512;
            ng_split<<<dim3(nb, B), 256>>>(bufA, mean_, istd_, gr + (i + 1) * 512,
                                           brr + (i + 1) * 512, xt_, ps, Lo, 512, 32);
        } else {
            ng_inplace<<<dim3(nb, B), 256>>>(bufA, mean_, istd_, gr + 5 * 512,
                                             brr + 5 * 512, Lo, 512, 32);
        }
    }

    int S = L[6];           // 976
    int NS = B * S;         // 7808

    // projection: feats[NS][1536]
    gemm_nt<<<dim3(1536 / 64, NS / 64), 128>>>(bufA, pw, pb, bufB, 512, 1536);

    // VQ
    float* sc = (float*)xt_;
    gemm_nt<<<dim3(1024 / 64, NS / 64), 128>>>(bufB, cbk, nullptr, sc, 1536, 1024);
    vq_argmin<<<(NS + 7) / 8, 256>>>(sc, cn_, idx_, NS);

    final_ln<<<NS, 256>>>(cbk, idx_, pos, mod, lng, lnb, out, S, NS);
}

// round 16
// speedup vs baseline: 1.3048x; 1.3048x over previous
#include <cuda_runtime.h>
#include <cuda_fp16.h>
#include <cuda_bf16.h>
#include <math.h>
#include <stdint.h>

__device__ float          g_bufA[128000000];
__device__ float          g_bufB[16000000];
__device__ __nv_bfloat16  g_xt[384000000];    // reused as __half planes
__device__ __nv_bfloat16  g_ws[43300000];     // reused as __half split weights
__device__ float          g_mean[512];
__device__ float          g_istd[512];
__device__ float          g_cnorm[1024];
__device__ int            g_idx[8192];

__device__ __forceinline__ float gelu_f(float x) {
    return 0.5f * x * (1.0f + erff(x * 0.7071067811865476f));
}
__device__ __forceinline__ uint32_t smem_u32(const void* p) {
    uint32_t a;
    asm("{ .reg .u64 t; cvta.to.shared.u64 t, %1; cvt.u32.u64 %0, t; }" : "=r"(a) : "l"(p));
    return a;
}
__device__ __forceinline__ void cpa16(uint32_t dst, const void* src) {
    asm volatile("cp.async.cg.shared.global [%0], [%1], 16;" :: "r"(dst), "l"(src));
}
__device__ __forceinline__ void cpa16z(uint32_t dst, const void* src, uint32_t sz) {
    asm volatile("cp.async.cg.shared.global [%0], [%1], 16, %2;" :: "r"(dst), "l"(src), "r"(sz));
}
__device__ __forceinline__ void ldmx4(uint32_t a, uint32_t* r) {
    asm volatile("ldmatrix.sync.aligned.m8n8.x4.shared.b16 {%0,%1,%2,%3}, [%4];"
                 : "=r"(r[0]), "=r"(r[1]), "=r"(r[2]), "=r"(r[3]) : "r"(a));
}
__device__ __forceinline__ void mma16816(float* c, const uint32_t* a, uint32_t b0, uint32_t b1) {
    asm volatile("mma.sync.aligned.m16n8k16.row.col.f32.f16.f16.f32 "
                 "{%0,%1,%2,%3}, {%4,%5,%6,%7}, {%8,%9}, {%0,%1,%2,%3};"
                 : "+f"(c[0]), "+f"(c[1]), "+f"(c[2]), "+f"(c[3])
                 : "r"(a[0]), "r"(a[1]), "r"(a[2]), "r"(a[3]), "r"(b0), "r"(b1));
}

struct f32x2 { unsigned long long u; };
__device__ __forceinline__ f32x2 pack2(float lo, float hi) {
    f32x2 r; asm("mov.b64 %0, {%1, %2};" : "=l"(r.u) : "f"(lo), "f"(hi)); return r;
}
__device__ __forceinline__ void fma2(f32x2 &d, f32x2 a, f32x2 b) {
    asm("fma.rn.f32x2 %0, %1, %2, %0;" : "+l"(d.u) : "l"(a.u), "l"(b.u));
}
__device__ __forceinline__ void unpack2(f32x2 v, float &lo, float &hi) {
    asm("mov.b64 {%0, %1}, %2;" : "=f"(lo), "=f"(hi) : "l"(v.u));
}

// conv0: Cin=1 -> yT[b][l][256]
__global__ __launch_bounds__(256)
void conv0_t(const float* __restrict__ x, const float* __restrict__ w,
             const float* __restrict__ bias, float* __restrict__ yT, int Lin, int Lout)
{
    __shared__ float Wsh[2560];
    __shared__ float Xsh[85];
    int b = blockIdx.y, l0 = blockIdx.x * 16, co = threadIdx.x;
    for (int i = co; i < 2560; i += 256) Wsh[i] = w[i];
    int g0 = 5 * l0 - 5;
    for (int i = co; i < 85; i += 256) {
        int gl = g0 + i;
        Xsh[i] = (gl >= 0 && gl < Lin) ? x[(size_t)b * Lin + gl] : 0.0f;
    }
    __syncthreads();
    float wr[10];
    #pragma unroll
    for (int t = 0; t < 10; t++) wr[t] = Wsh[co * 10 + t];
    float bv = bias[co];
    for (int j = 0; j < 16; j++) {
        int l = l0 + j;
        if (l >= Lout) break;
        float a = bv;
        #pragma unroll
        for (int t = 0; t < 10; t++) a = fmaf(wr[t], Xsh[5 * j + t], a);
        yT[((size_t)b * Lout + l) * 256 + co] = a;
    }
}

// All 6 layers' weights -> fp16 2-comp split SCALED x16, layout [comp][co][t][ci]
__global__ __launch_bounds__(256)
void wprep_all(const float* __restrict__ w1, const float* __restrict__ wr,
               __half* __restrict__ d)
{
    int L = blockIdx.y, co = blockIdx.x;
    int Cin = (L == 0) ? 256 : 512;
    const float* src = (L == 0) ? w1 : wr + (size_t)(L - 1) * 512 * 512 * 10;
    __half* dst = (L == 0) ? d : d + 2621440 + (size_t)(L - 1) * 5242880;
    size_t cs = (size_t)512 * 10 * Cin;
    for (int i = threadIdx.x; i < Cin * 10; i += 256) {
        int ci = i / 10, t = i - ci * 10;
        float v = 16.0f * src[((size_t)co * Cin + ci) * 10 + t];
        __half c0 = __float2half(v);
        __half c1 = __float2half(v - __half2float(c0));
        size_t o = ((size_t)co * 10 + t) * Cin + ci;
        dst[o] = c0; dst[cs + o] = c1;
    }
}

// ---------------------------------------------------------------------------
// mma.sync fp16 conv. CTA 256thr/8 warps; tile M=128(l) x N=64(co); warp 32x32.
// K-chunk = 128 ci per tap (8 k16 steps). Weights pre-scaled x16, activations
// split unscaled -> all 3 products {x0w0',x0w1',x1w0'} share ONE fp32 acc set;
// drain g = fma(c, 1/16, g) every 2 chunks. 2-stage cp.async pipeline;
// incremental-pointer loads for interior CTAs (+128 halves per chunk).
// ---------------------------------------------------------------------------
#define ROWB   272            // 256B data + 16B pad (conflict-free ldmatrix)
#define ACMP   34816          // 128 rows * 272B
#define BCMP   17408          // 64 rows * 272B
#define AHALF  69632          // 2 A comps
#define BUFB   104448         // A(2) + B(2)
#define NSTG   2

template<int CIN>
__global__ __launch_bounds__(256)
void conv_mma(const __half* __restrict__ xs, size_t planeStride,
              const __half* __restrict__ ws, size_t wcs,
              const float* __restrict__ bias, float* __restrict__ yT,
              int Cout, int Lin, int Lout)
{
    extern __shared__ __align__(128) char smem[];
    uint32_t sbase = smem_u32(smem);
    int tid = threadIdx.x, wid = tid >> 5, lane = tid & 31;
    int wm = wid & 3, wn = wid >> 2;          // 4 x 2 warp grid
    int co0 = blockIdx.x * 64;
    int l0  = blockIdx.y * 128;
    int b   = blockIdx.z;

    const __half* xb = xs + (size_t)b * (size_t)Lin * CIN;
    constexpr int NKB = (CIN == 256) ? 1 : 2;   // log2(chunks of 128 per tap)
    constexpr int NKC = 1 << NKB;
    constexpr int NC  = 10 * NKC;

    float c[2][4][4];     // single working accumulator set
    float g[2][4][4];     // grand accumulators (true scale)
    #pragma unroll
    for (int i = 0; i < 2; i++)
        #pragma unroll
        for (int j = 0; j < 4; j++)
            #pragma unroll
            for (int q = 0; q < 4; q++) { c[i][j][q] = 0.0f; g[i][j][q] = 0.0f; }

    // ---- compute body for chunk kk (shared by both load paths) ----
    #define COMPUTE(kk) do {                                                          \
        int _kc = (kk);                                                               \
        uint32_t Ab = sbase + (_kc & 1) * BUFB;                                       \
        uint32_t Bb = Ab + AHALF;                                                     \
        uint32_t aw = Ab + (wm * 32 + (lane & 15)) * ROWB + (lane >> 4) * 16;         \
        uint32_t bw = Bb + (wn * 32 + ((lane >> 4) << 3) + (lane & 7)) * ROWB         \
                        + ((lane >> 3) & 1) * 16;                                     \
        _Pragma("unroll")                                                             \
        for (int ks = 0; ks < 8; ks++) {                                              \
            uint32_t a[2][2][4], bf[2][2][4];                                         \
            _Pragma("unroll")                                                         \
            for (int cp = 0; cp < 2; cp++)                                            \
                _Pragma("unroll")                                                     \
                for (int mt = 0; mt < 2; mt++)                                        \
                    ldmx4(aw + cp * ACMP + mt * (16 * ROWB) + ks * 32, a[cp][mt]);    \
            _Pragma("unroll")                                                         \
            for (int cp = 0; cp < 2; cp++)                                            \
                _Pragma("unroll")                                                     \
                for (int n2 = 0; n2 < 2; n2++)                                        \
                    ldmx4(bw + cp * BCMP + n2 * (16 * ROWB) + ks * 32, bf[cp][n2]);   \
            _Pragma("unroll")                                                         \
            for (int mt = 0; mt < 2; mt++)                                            \
                _Pragma("unroll")                                                     \
                for (int nt = 0; nt < 4; nt++) {                                      \
                    uint32_t b0a = bf[0][nt >> 1][(nt & 1) * 2];                      \
                    uint32_t b0b = bf[0][nt >> 1][(nt & 1) * 2 + 1];                  \
                    uint32_t b1a = bf[1][nt >> 1][(nt & 1) * 2];                      \
                    uint32_t b1b = bf[1][nt >> 1][(nt & 1) * 2 + 1];                  \
                    mma16816(c[mt][nt], a[0][mt], b0a, b0b);                          \
                    mma16816(c[mt][nt], a[0][mt], b1a, b1b);                          \
                    mma16816(c[mt][nt], a[1][mt], b0a, b0b);                          \
                }                                                                     \
        }                                                                             \
        if ((_kc & 1) == 1 || _kc == NC - 1) {                                        \
            _Pragma("unroll")                                                         \
            for (int mt = 0; mt < 2; mt++)                                            \
                _Pragma("unroll")                                                     \
                for (int nt = 0; nt < 4; nt++)                                        \
                    _Pragma("unroll")                                                 \
                    for (int q = 0; q < 4; q++) {                                     \
                        g[mt][nt][q] = fmaf(c[mt][nt][q], 0.0625f, g[mt][nt][q]);     \
                        c[mt][nt][q] = 0.0f;                                          \
                    }                                                                 \
        }                                                                             \
        __syncthreads();                                                              \
    } while (0)

    bool interior = (l0 >= 3) && (2 * l0 + 258 < Lin);

    if (interior) {
        // incremental-pointer fast path: both A and B advance +128 halves/chunk
        int row0 = tid >> 4, seg = tid & 15;
        const __half* pA = xb + (size_t)(2 * l0 - 5 + 2 * row0) * CIN + (seg << 3);
        const __half* pB = ws + ((size_t)(co0 + row0) * 10) * CIN + (seg << 3);
        uint32_t smA = (uint32_t)(row0 * ROWB + (seg << 4));
        int fsi = 0;
        #define ISSUE_F() do {                                                        \
            uint32_t Ab = sbase + (uint32_t)(fsi & 1) * BUFB + smA;                   \
            uint32_t Bb = sbase + (uint32_t)(fsi & 1) * BUFB + AHALF + smA;           \
            _Pragma("unroll")                                                         \
            for (int cp = 0; cp < 2; cp++)                                            \
                _Pragma("unroll")                                                     \
                for (int jj = 0; jj < 8; jj++)                                        \
                    cpa16(Ab + cp * ACMP + jj * (16 * ROWB),                          \
                          pA + (size_t)cp * planeStride + jj * (32 * CIN));           \
            _Pragma("unroll")                                                         \
            for (int cp = 0; cp < 2; cp++)                                            \
                _Pragma("unroll")                                                     \
                for (int jj = 0; jj < 4; jj++)                                        \
                    cpa16(Bb + cp * BCMP + jj * (16 * ROWB),                          \
                          pB + (size_t)cp * wcs + jj * (160 * CIN));                  \
            asm volatile("cp.async.commit_group;" ::: "memory");                      \
            pA += 128; pB += 128; fsi++;                                              \
        } while (0)
        ISSUE_F();
        for (int k = 0; k < NC; k++) {
            if (k + 1 < NC) {
                ISSUE_F();
                asm volatile("cp.async.wait_group 1;" ::: "memory");
            } else {
                asm volatile("cp.async.wait_group 0;" ::: "memory");
            }
            __syncthreads();
            COMPUTE(k);
        }
    } else {
        #define ISSUE_S(kk) do {                                                      \
            int _k = (kk);                                                            \
            int _s = _k & 1, _t = _k >> NKB, _ci0 = (_k & (NKC - 1)) << 7;            \
            uint32_t Ab = sbase + _s * BUFB;                                          \
            uint32_t Bb = Ab + AHALF;                                                 \
            int _r0 = 2 * l0 - 5 + _t;                                                \
            _Pragma("unroll")                                                         \
            for (int j = 0; j < 16; j++) {                                            \
                int idx = tid + j * 256;                                              \
                int comp = idx >> 11, rem = idx & 2047;                               \
                int row = rem >> 4, sg = rem & 15;                                    \
                int r = _r0 + 2 * row;                                                \
                int ok = (r >= 0 && r < Lin);                                         \
                const __half* sa = xb + (size_t)comp * planeStride                    \
                    + (size_t)(ok ? r : 0) * CIN + _ci0 + (sg << 3);                  \
                cpa16z(Ab + comp * ACMP + row * ROWB + (sg << 4), sa, ok ? 16u : 0u); \
            }                                                                         \
            _Pragma("unroll")                                                         \
            for (int j = 0; j < 8; j++) {                                             \
                int idx = tid + j * 256;                                              \
                int comp = idx >> 10, rem = idx & 1023;                               \
                int row = rem >> 4, sg = rem & 15;                                    \
                const __half* sbp = ws + (size_t)comp * wcs                           \
                    + ((size_t)(co0 + row) * 10 + _t) * CIN + _ci0 + (sg << 3);       \
                cpa16(Bb + comp * BCMP + row * ROWB + (sg << 4), sbp);                \
            }                                                                         \
            asm volatile("cp.async.commit_group;" ::: "memory");                      \
        } while (0)
        ISSUE_S(0);
        for (int k = 0; k < NC; k++) {
            if (k + 1 < NC) {
                ISSUE_S(k + 1);
                asm volatile("cp.async.wait_group 1;" ::: "memory");
            } else {
                asm volatile("cp.async.wait_group 0;" ::: "memory");
            }
            __syncthreads();
            COMPUTE(k);
        }
    }

    #pragma unroll
    for (int mt = 0; mt < 2; mt++) {
        int lr = l0 + wm * 32 + mt * 16 + (lane >> 2);
        #pragma unroll
        for (int nt = 0; nt < 4; nt++) {
            int col = co0 + wn * 32 + nt * 8 + (lane & 3) * 2;
            float b0 = bias[col], b1 = bias[col + 1];
            if (lr < Lout) {
                float2 v = make_float2(g[mt][nt][0] + b0, g[mt][nt][1] + b1);
                *(float2*)&yT[((size_t)b * Lout + lr) * Cout + col] = v;
            }
            if (lr + 8 < Lout) {
                float2 v = make_float2(g[mt][nt][2] + b0, g[mt][nt][3] + b1);
                *(float2*)&yT[((size_t)b * Lout + lr + 8) * Cout + col] = v;
            }
        }
    }
}

// GN stats over [b][l][C]
__global__ __launch_bounds__(256)
void gn_stats_t(const float* __restrict__ x, float* __restrict__ mean,
                float* __restrict__ istd, int L, int C, int G)
{
    int blk = blockIdx.x, b = blk / G, g = blk % G;
    const float* p = x + (size_t)b * L * C + g * 16;
    float s = 0.0f, s2 = 0.0f;
    int tot = L * 16;
    for (int i = threadIdx.x; i < tot; i += 256) {
        int l = i >> 4, cc = i & 15;
        float v = p[(size_t)l * C + cc];
        s += v; s2 = fmaf(v, v, s2);
    }
    __shared__ float sa[256], sbm[256];
    int tid = threadIdx.x;
    sa[tid] = s; sbm[tid] = s2;
    __syncthreads();
    for (int o = 128; o > 0; o >>= 1) {
        if (tid < o) { sa[tid] += sa[tid + o]; sbm[tid] += sbm[tid + o]; }
        __syncthreads();
    }
    if (tid == 0) {
        float m = sa[0] / (float)tot;
        float var = sbm[0] / (float)tot - m * m;
        mean[blk] = m;
        istd[blk] = rsqrtf(var + 1e-5f);
    }
}

// GN apply + GELU + unscaled fp16 2-way split -> planes
__global__ __launch_bounds__(256)
void ng_split(const float* __restrict__ x, const float* __restrict__ mean,
              const float* __restrict__ istd, const float* __restrict__ gma,
              const float* __restrict__ bta, __half* __restrict__ xs,
              size_t ps, int L, int C, int G)
{
    int b = blockIdx.y;
    size_t i4 = (size_t)blockIdx.x * 256 + threadIdx.x;
    size_t n4 = (size_t)L * C >> 2;
    if (i4 >= n4) return;
    size_t base = (size_t)b * L * C;
    float4 v = ((const float4*)(x + base))[i4];
    int cc = (int)((i4 << 2) % (size_t)C);
    int bg = b * G + (cc >> 4);
    float mu = mean[bg], is = istd[bg];
    float o[4] = {v.x, v.y, v.z, v.w};
    __half p0[4], p1[4];
    #pragma unroll
    for (int j = 0; j < 4; j++) {
        float h = gelu_f((o[j] - mu) * is * gma[cc + j] + bta[cc + j]);
        __half a = __float2half(h);
        p0[j] = a;
        p1[j] = __float2half(h - __half2float(a));
    }
    ((uint64_t*)(xs + base))[i4]      = *(uint64_t*)p0;
    ((uint64_t*)(xs + ps + base))[i4] = *(uint64_t*)p1;
}

__global__ __launch_bounds__(256)
void ng_inplace(float* __restrict__ x, const float* __restrict__ mean,
                const float* __restrict__ istd, const float* __restrict__ gma,
                const float* __restrict__ bta, int L, int C, int G)
{
    int b = blockIdx.y;
    size_t i4 = (size_t)blockIdx.x * 256 + threadIdx.x;
    size_t n4 = (size_t)L * C >> 2;
    if (i4 >= n4) return;
    size_t base = (size_t)b * L * C;
    float4 v = ((const float4*)(x + base))[i4];
    int cc = (int)((i4 << 2) % (size_t)C);
    int bg = b * G + (cc >> 4);
    float mu = mean[bg], is = istd[bg];
    v.x = gelu_f((v.x - mu) * is * gma[cc + 0] + bta[cc + 0]);
    v.y = gelu_f((v.y - mu) * is * gma[cc + 1] + bta[cc + 1]);
    v.z = gelu_f((v.z - mu) * is * gma[cc + 2] + bta[cc + 2]);
    v.w = gelu_f((v.w - mu) * is * gma[cc + 3] + bta[cc + 3]);
    ((float4*)(x + base))[i4] = v;
}

// SIMT f32x2 GEMM tail
__global__ __launch_bounds__(128)
void gemm_nt(const float* __restrict__ A, const float* __restrict__ B,
             const float* __restrict__ bias, float* __restrict__ out, int K, int Nj)
{
    __shared__ float As[64][17], Bs[64][17];
    int tid = threadIdx.x;
    int i0 = blockIdx.y * 64, j0 = blockIdx.x * 64;
    int isub = tid >> 4, jsub = tid & 15;
    f32x2 acc[8][2];
    #pragma unroll
    for (int i = 0; i < 8; i++) { acc[i][0].u = 0ull; acc[i][1].u = 0ull; }
    for (int k0 = 0; k0 < K; k0 += 16) {
        __syncthreads();
        for (int x = tid; x < 1024; x += 128) {
            int r = x >> 4, cc = x & 15;
            As[r][cc] = A[(size_t)(i0 + r) * K + k0 + cc];
            Bs[r][cc] = B[(size_t)(j0 + r) * K + k0 + cc];
        }
        __syncthreads();
        #pragma unroll 4
        for (int k = 0; k < 16; k++) {
            f32x2 b0 = pack2(Bs[jsub * 4 + 0][k], Bs[jsub * 4 + 1][k]);
            f32x2 b1 = pack2(Bs[jsub * 4 + 2][k], Bs[jsub * 4 + 3][k]);
            #pragma unroll
            for (int ii = 0; ii < 8; ii++) {
                float a = As[isub + (ii << 3)][k];
                f32x2 a2 = pack2(a, a);
                fma2(acc[ii][0], a2, b0);
                fma2(acc[ii][1], a2, b1);
            }
        }
    }
    int j = j0 + jsub * 4;
    float bv0 = bias ? bias[j] : 0.0f, bv1 = bias ? bias[j + 1] : 0.0f;
    float bv2 = bias ? bias[j + 2] : 0.0f, bv3 = bias ? bias[j + 3] : 0.0f;
    #pragma unroll
    for (int ii = 0; ii < 8; ii++) {
        int i = i0 + isub + (ii << 3);
        float o0, o1, o2, o3;
        unpack2(acc[ii][0], o0, o1);
        unpack2(acc[ii][1], o2, o3);
        float* p = out + (size_t)i * Nj + j;
        p[0] = o0 + bv0; p[1] = o1 + bv1; p[2] = o2 + bv2; p[3] = o3 + bv3;
    }
}

__global__ __launch_bounds__(256)
void cb_norms(const float* __restrict__ cbk, float* __restrict__ cn)
{
    const float4* row = (const float4*)(cbk + (size_t)blockIdx.x * 1536);
    float s = 0.0f;
    for (int i = threadIdx.x; i < 384; i += 256) {
        float4 v = row[i];
        s += v.x * v.x + v.y * v.y + v.z * v.z + v.w * v.w;
    }
    __shared__ float sa[256];
    int tid = threadIdx.x;
    sa[tid] = s;
    __syncthreads();
    for (int o = 128; o > 0; o >>= 1) {
        if (tid < o) sa[tid] += sa[tid + o];
        __syncthreads();
    }
    if (tid == 0) cn[blockIdx.x] = sa[0];
}

__global__ __launch_bounds__(256)
void vq_argmin(const float* __restrict__ sc, const float* __restrict__ cn,
               int* __restrict__ idx, int NS)
{
    int g = blockIdx.x * 8 + (threadIdx.x >> 5);
    int lane = threadIdx.x & 31;
    if (g >= NS) return;
    const float* s = sc + (size_t)g * 1024;
    float best = 3.4e38f; int bi = 1 << 30;
    for (int j = lane; j < 1024; j += 32) {
        float d = fmaf(-2.0f, s[j], cn[j]);
        if (d < best) { best = d; bi = j; }
    }
    #pragma unroll
    for (int o = 16; o > 0; o >>= 1) {
        float ov = __shfl_xor_sync(0xffffffffu, best, o);
        int   oi = __shfl_xor_sync(0xffffffffu, bi,   o);
        if (ov < best || (ov == best && oi < bi)) { best = ov; bi = oi; }
    }
    if (lane == 0) idx[g] = bi;
}

__global__ __launch_bounds__(256)
void final_ln(const float* __restrict__ cbk, const int* __restrict__ idx,
              const float* __restrict__ pos, const float* __restrict__ mod,
              const float* __restrict__ lng, const float* __restrict__ lnb,
              float* __restrict__ out, int S, int NS)
{
    int n = blockIdx.x, s = n % S, tid = threadIdx.x;
    __shared__ float row[1536];
    __shared__ float sa[256], sbm[256];
    const float* c = cbk + (size_t)idx[n] * 1536;
    const float* p = pos + (size_t)s * 1536;
    float ls = 0.0f, ls2 = 0.0f;
    for (int e = tid; e < 1536; e += 256) {
        float v = c[e] + p[e] + mod[e];
        row[e] = v;
        ls += v; ls2 = fmaf(v, v, ls2);
    }
    sa[tid] = ls; sbm[tid] = ls2;
    __syncthreads();
    for (int o = 128; o > 0; o >>= 1) {
        if (tid < o) { sa[tid] += sa[tid + o]; sbm[tid] += sbm[tid + o]; }
        __syncthreads();
    }
    float m = sa[0] * (1.0f / 1536.0f);
    float var = sbm[0] * (1.0f / 1536.0f) - m * m;
    float r = rsqrtf(var + 1e-5f);
    for (int e = tid; e < 1536; e += 256)
        out[(size_t)n * 1536 + e] = (row[e] - m) * r * lng[e] + lnb[e];
    if (tid == 0) {
        out[(size_t)NS * 1536 + n]      = 1.0f;
        out[(size_t)NS * 1536 + NS + n] = (float)idx[n];
    }
}

extern "C" void kernel_launch(void* const* d_in, const int* in_sizes, int n_in,
                              void* d_out, int out_size)
{
    const float* wav = (const float*)d_in[0];
    const float* w0  = (const float*)d_in[1];
    const float* b0  = (const float*)d_in[2];
    const float* w1  = (const float*)d_in[3];
    const float* b1  = (const float*)d_in[4];
    const float* wr  = (const float*)d_in[5];
    const float* br  = (const float*)d_in[6];
    const float* g0  = (const float*)d_in[7];
    const float* bb0 = (const float*)d_in[8];
    const float* gr  = (const float*)d_in[9];
    const float* brr = (const float*)d_in[10];
    const float* pw  = (const float*)d_in[11];
    const float* pb  = (const float*)d_in[12];
    const float* cbk = (const float*)d_in[13];
    const float* pos = (const float*)d_in[14];
    const float* mod = (const float*)d_in[15];
    const float* lng = (const float*)d_in[16];
    const float* lnb = (const float*)d_in[17];
    float* out = (float*)d_out;

    const int B = 8;
    int Lw = in_sizes[0] / B;
    int L[7];
    L[0] = Lw / 5 + 1;
    for (int i = 1; i <= 6; i++) L[i] = L[i - 1] / 2 + 1;

    float *bufA, *bufB, *mean_, *istd_, *cn_;
    __half *xt_, *ws_;
    int *idx_;
    cudaGetSymbolAddress((void**)&bufA,  g_bufA);
    cudaGetSymbolAddress((void**)&bufB,  g_bufB);
    cudaGetSymbolAddress((void**)&xt_,   g_xt);
    cudaGetSymbolAddress((void**)&ws_,   g_ws);
    cudaGetSymbolAddress((void**)&mean_, g_mean);
    cudaGetSymbolAddress((void**)&istd_, g_istd);
    cudaGetSymbolAddress((void**)&cn_,   g_cnorm);
    cudaGetSymbolAddress((void**)&idx_,  g_idx);

    const int SMEMSZ = NSTG * BUFB;   // 208896
    cudaFuncSetAttribute(conv_mma<256>, cudaFuncAttributeMaxDynamicSharedMemorySize, SMEMSZ);
    cudaFuncSetAttribute(conv_mma<512>, cudaFuncAttributeMaxDynamicSharedMemorySize, SMEMSZ);

    cb_norms<<<1024, 256>>>(cbk, cn_);
    wprep_all<<<dim3(512, 6), 256>>>(w1, wr, ws_);

    conv0_t<<<dim3((L[0] + 15) / 16, B), 256>>>(wav, w0, b0, bufA, Lw, L[0]);
    gn_stats_t<<<B * 16, 256>>>(bufA, mean_, istd_, L[0], 256, 16);
    {
        size_t ps = (size_t)B * L[0] * 256;
        int nb = (int)(((size_t)L[0] * 256 / 4 + 255) / 256);
        ng_split<<<dim3(nb, B), 256>>>(bufA, mean_, istd_, g0, bb0, xt_, ps, L[0], 256, 16);
    }

    // layer 1 (MMA, Cin=256)
    conv_mma<256><<<dim3(8, (L[1] + 127) / 128, B), 256, SMEMSZ>>>(
        xt_, (size_t)B * L[0] * 256, ws_, 1310720, b1, bufA, 512, L[0], L[1]);
    gn_stats_t<<<B * 32, 256>>>(bufA, mean_, istd_, L[1], 512, 32);
    {
        size_t ps = (size_t)B * L[1] * 512;
        int nb = (int)(((size_t)L[1] * 512 / 4 + 255) / 256);
        ng_split<<<dim3(nb, B), 256>>>(bufA, mean_, istd_, gr, brr, xt_, ps, L[1], 512, 32);
    }

    // layers 2..6 (MMA, Cin=512)
    for (int i = 0; i < 5; i++) {
        int Lin = L[1 + i], Lo = L[2 + i];
        conv_mma<512><<<dim3(8, (Lo + 127) / 128, B), 256, SMEMSZ>>>(
            xt_, (size_t)B * Lin * 512, ws_ + 2621440 + (size_t)i * 5242880, 2621440,
            br + i * 512, bufA, 512, Lin, Lo);
        gn_stats_t<<<B * 32, 256>>>(bufA, mean_, istd_, Lo, 512, 32);
        int nb = (int)(((size_t)Lo * 512 / 4 + 255) / 256);
        if (i < 4) {
            size_t ps = (size_t)B * Lo * 512;
            ng_split<<<dim3(nb, B), 256>>>(bufA, mean_, istd_, gr + (i + 1) * 512,
                                           brr + (i + 1) * 512, xt_, ps, Lo, 512, 32);
        } else {
            ng_inplace<<<dim3(nb, B), 256>>>(bufA, mean_, istd_, gr + 5 * 512,
                                             brr + 5 * 512, Lo, 512, 32);
        }
    }

    int S = L[6];           // 976
    int NS = B * S;         // 7808

    // projection: feats[NS][1536]
    gemm_nt<<<dim3(1536 / 64, NS / 64), 128>>>(bufA, pw, pb, bufB, 512, 1536);

    // VQ
    float* sc = (float*)xt_;
    gemm_nt<<<dim3(1024 / 64, NS / 64), 128>>>(bufB, cbk, nullptr, sc, 1536, 1024);
    vq_argmin<<<(NS + 7) / 8, 256>>>(sc, cn_, idx_, NS);

    final_ln<<<NS, 256>>>(cbk, idx_, pos, mod, lng, lnb, out, S, NS);
}

// round 17
// speedup vs baseline: 1.3572x; 1.0401x over previous
#include <cuda_runtime.h>
#include <cuda_fp16.h>
#include <cuda_bf16.h>
#include <math.h>
#include <stdint.h>

__device__ float          g_bufA[128000000];
__device__ float          g_bufB[16000000];
__device__ __nv_bfloat16  g_xt[384000000];    // __half planes (activations, feats)
__device__ __nv_bfloat16  g_ws[43300000];     // __half split weights (+pw/cbk planes)
__device__ float          g_mean[512];
__device__ float          g_istd[512];
__device__ float          g_cnorm[1024];
__device__ int            g_idx[8192];

__device__ __forceinline__ float gelu_f(float x) {
    return 0.5f * x * (1.0f + erff(x * 0.7071067811865476f));
}
__device__ __forceinline__ uint32_t smem_u32(const void* p) {
    uint32_t a;
    asm("{ .reg .u64 t; cvta.to.shared.u64 t, %1; cvt.u32.u64 %0, t; }" : "=r"(a) : "l"(p));
    return a;
}
__device__ __forceinline__ void cpa16(uint32_t dst, const void* src) {
    asm volatile("cp.async.cg.shared.global [%0], [%1], 16;" :: "r"(dst), "l"(src));
}
__device__ __forceinline__ void cpa16z(uint32_t dst, const void* src, uint32_t sz) {
    asm volatile("cp.async.cg.shared.global [%0], [%1], 16, %2;" :: "r"(dst), "l"(src), "r"(sz));
}
__device__ __forceinline__ void ldmx4(uint32_t a, uint32_t* r) {
    asm volatile("ldmatrix.sync.aligned.m8n8.x4.shared.b16 {%0,%1,%2,%3}, [%4];"
                 : "=r"(r[0]), "=r"(r[1]), "=r"(r[2]), "=r"(r[3]) : "r"(a));
}
__device__ __forceinline__ void mma16816(float* c, const uint32_t* a, uint32_t b0, uint32_t b1) {
    asm volatile("mma.sync.aligned.m16n8k16.row.col.f32.f16.f16.f32 "
                 "{%0,%1,%2,%3}, {%4,%5,%6,%7}, {%8,%9}, {%0,%1,%2,%3};"
                 : "+f"(c[0]), "+f"(c[1]), "+f"(c[2]), "+f"(c[3])
                 : "r"(a[0]), "r"(a[1]), "r"(a[2]), "r"(a[3]), "r"(b0), "r"(b1));
}

// conv0: Cin=1 -> yT[b][l][256]
__global__ __launch_bounds__(256)
void conv0_t(const float* __restrict__ x, const float* __restrict__ w,
             const float* __restrict__ bias, float* __restrict__ yT, int Lin, int Lout)
{
    __shared__ float Wsh[2560];
    __shared__ float Xsh[85];
    int b = blockIdx.y, l0 = blockIdx.x * 16, co = threadIdx.x;
    for (int i = co; i < 2560; i += 256) Wsh[i] = w[i];
    int g0 = 5 * l0 - 5;
    for (int i = co; i < 85; i += 256) {
        int gl = g0 + i;
        Xsh[i] = (gl >= 0 && gl < Lin) ? x[(size_t)b * Lin + gl] : 0.0f;
    }
    __syncthreads();
    float wr[10];
    #pragma unroll
    for (int t = 0; t < 10; t++) wr[t] = Wsh[co * 10 + t];
    float bv = bias[co];
    for (int j = 0; j < 16; j++) {
        int l = l0 + j;
        if (l >= Lout) break;
        float a = bv;
        #pragma unroll
        for (int t = 0; t < 10; t++) a = fmaf(wr[t], Xsh[5 * j + t], a);
        yT[((size_t)b * Lout + l) * 256 + co] = a;
    }
}

// Conv weights -> fp16 2-comp split SCALED x16, layout [comp][co][t][ci]
__global__ __launch_bounds__(256)
void wprep_all(const float* __restrict__ w1, const float* __restrict__ wr,
               __half* __restrict__ d)
{
    int L = blockIdx.y, co = blockIdx.x;
    int Cin = (L == 0) ? 256 : 512;
    const float* src = (L == 0) ? w1 : wr + (size_t)(L - 1) * 512 * 512 * 10;
    __half* dst = (L == 0) ? d : d + 2621440 + (size_t)(L - 1) * 5242880;
    size_t cs = (size_t)512 * 10 * Cin;
    for (int i = threadIdx.x; i < Cin * 10; i += 256) {
        int ci = i / 10, t = i - ci * 10;
        float v = 16.0f * src[((size_t)co * Cin + ci) * 10 + t];
        __half c0 = __float2half(v);
        __half c1 = __float2half(v - __half2float(c0));
        size_t o = ((size_t)co * 10 + t) * Cin + ci;
        dst[o] = c0; dst[cs + o] = c1;
    }
}

// Generic matrix [R][K] fp32 -> fp16 planes scaled x16 (for pw, cbk)
__global__ __launch_bounds__(256)
void msplit(const float* __restrict__ src, __half* __restrict__ dst, int K)
{
    int r = blockIdx.x;
    size_t cs = (size_t)gridDim.x * K;
    for (int i = threadIdx.x; i < K; i += 256) {
        float v = 16.0f * src[(size_t)r * K + i];
        __half c0 = __float2half(v);
        dst[(size_t)r * K + i] = c0;
        dst[cs + (size_t)r * K + i] = __float2half(v - __half2float(c0));
    }
}

#define ROWB   272
#define ACMP   34816
#define BCMP   17408
#define AHALF  69632
#define BUFB   104448
#define NSTG   2

// ---------------------------------------------------------------------------
// conv_mma: byte-identical to round-16 winner.
// ---------------------------------------------------------------------------
template<int CIN>
__global__ __launch_bounds__(256)
void conv_mma(const __half* __restrict__ xs, size_t planeStride,
              const __half* __restrict__ ws, size_t wcs,
              const float* __restrict__ bias, float* __restrict__ yT,
              int Cout, int Lin, int Lout)
{
    extern __shared__ __align__(128) char smem[];
    uint32_t sbase = smem_u32(smem);
    int tid = threadIdx.x, wid = tid >> 5, lane = tid & 31;
    int wm = wid & 3, wn = wid >> 2;
    int co0 = blockIdx.x * 64;
    int l0  = blockIdx.y * 128;
    int b   = blockIdx.z;

    const __half* xb = xs + (size_t)b * (size_t)Lin * CIN;
    constexpr int NKB = (CIN == 256) ? 1 : 2;
    constexpr int NKC = 1 << NKB;
    constexpr int NC  = 10 * NKC;

    float c[2][4][4];
    float g[2][4][4];
    #pragma unroll
    for (int i = 0; i < 2; i++)
        #pragma unroll
        for (int j = 0; j < 4; j++)
            #pragma unroll
            for (int q = 0; q < 4; q++) { c[i][j][q] = 0.0f; g[i][j][q] = 0.0f; }

    #define COMPUTE(kk) do {                                                          \
        int _kc = (kk);                                                               \
        uint32_t Ab = sbase + (_kc & 1) * BUFB;                                       \
        uint32_t Bb = Ab + AHALF;                                                     \
        uint32_t aw = Ab + (wm * 32 + (lane & 15)) * ROWB + (lane >> 4) * 16;         \
        uint32_t bw = Bb + (wn * 32 + ((lane >> 4) << 3) + (lane & 7)) * ROWB         \
                        + ((lane >> 3) & 1) * 16;                                     \
        _Pragma("unroll")                                                             \
        for (int ks = 0; ks < 8; ks++) {                                              \
            uint32_t a[2][2][4], bf[2][2][4];                                         \
            _Pragma("unroll")                                                         \
            for (int cp = 0; cp < 2; cp++)                                            \
                _Pragma("unroll")                                                     \
                for (int mt = 0; mt < 2; mt++)                                        \
                    ldmx4(aw + cp * ACMP + mt * (16 * ROWB) + ks * 32, a[cp][mt]);    \
            _Pragma("unroll")                                                         \
            for (int cp = 0; cp < 2; cp++)                                            \
                _Pragma("unroll")                                                     \
                for (int n2 = 0; n2 < 2; n2++)                                        \
                    ldmx4(bw + cp * BCMP + n2 * (16 * ROWB) + ks * 32, bf[cp][n2]);   \
            _Pragma("unroll")                                                         \
            for (int mt = 0; mt < 2; mt++)                                            \
                _Pragma("unroll")                                                     \
                for (int nt = 0; nt < 4; nt++) {                                      \
                    uint32_t b0a = bf[0][nt >> 1][(nt & 1) * 2];                      \
                    uint32_t b0b = bf[0][nt >> 1][(nt & 1) * 2 + 1];                  \
                    uint32_t b1a = bf[1][nt >> 1][(nt & 1) * 2];                      \
                    uint32_t b1b = bf[1][nt >> 1][(nt & 1) * 2 + 1];                  \
                    mma16816(c[mt][nt], a[0][mt], b0a, b0b);                          \
                    mma16816(c[mt][nt], a[0][mt], b1a, b1b);                          \
                    mma16816(c[mt][nt], a[1][mt], b0a, b0b);                          \
                }                                                                     \
        }                                                                             \
        if ((_kc & 1) == 1 || _kc == NC - 1) {                                        \
            _Pragma("unroll")                                                         \
            for (int mt = 0; mt < 2; mt++)                                            \
                _Pragma("unroll")                                                     \
                for (int nt = 0; nt < 4; nt++)                                        \
                    _Pragma("unroll")                                                 \
                    for (int q = 0; q < 4; q++) {                                     \
                        g[mt][nt][q] = fmaf(c[mt][nt][q], 0.0625f, g[mt][nt][q]);     \
                        c[mt][nt][q] = 0.0f;                                          \
                    }                                                                 \
        }                                                                             \
        __syncthreads();                                                              \
    } while (0)

    bool interior = (l0 >= 3) && (2 * l0 + 258 < Lin);

    if (interior) {
        int row0 = tid >> 4, seg = tid & 15;
        const __half* pA = xb + (size_t)(2 * l0 - 5 + 2 * row0) * CIN + (seg << 3);
        const __half* pB = ws + ((size_t)(co0 + row0) * 10) * CIN + (seg << 3);
        uint32_t smA = (uint32_t)(row0 * ROWB + (seg << 4));
        int fsi = 0;
        #define ISSUE_F() do {                                                        \
            uint32_t Ab = sbase + (uint32_t)(fsi & 1) * BUFB + smA;                   \
            uint32_t Bb = sbase + (uint32_t)(fsi & 1) * BUFB + AHALF + smA;           \
            _Pragma("unroll")                                                         \
            for (int cp = 0; cp < 2; cp++)                                            \
                _Pragma("unroll")                                                     \
                for (int jj = 0; jj < 8; jj++)                                        \
                    cpa16(Ab + cp * ACMP + jj * (16 * ROWB),                          \
                          pA + (size_t)cp * planeStride + jj * (32 * CIN));           \
            _Pragma("unroll")                                                         \
            for (int cp = 0; cp < 2; cp++)                                            \
                _Pragma("unroll")                                                     \
                for (int jj = 0; jj < 4; jj++)                                        \
                    cpa16(Bb + cp * BCMP + jj * (16 * ROWB),                          \
                          pB + (size_t)cp * wcs + jj * (160 * CIN));                  \
            asm volatile("cp.async.commit_group;" ::: "memory");                      \
            pA += 128; pB += 128; fsi++;                                              \
        } while (0)
        ISSUE_F();
        for (int k = 0; k < NC; k++) {
            if (k + 1 < NC) {
                ISSUE_F();
                asm volatile("cp.async.wait_group 1;" ::: "memory");
            } else {
                asm volatile("cp.async.wait_group 0;" ::: "memory");
            }
            __syncthreads();
            COMPUTE(k);
        }
    } else {
        #define ISSUE_S(kk) do {                                                      \
            int _k = (kk);                                                            \
            int _s = _k & 1, _t = _k >> NKB, _ci0 = (_k & (NKC - 1)) << 7;            \
            uint32_t Ab = sbase + _s * BUFB;                                          \
            uint32_t Bb = Ab + AHALF;                                                 \
            int _r0 = 2 * l0 - 5 + _t;                                                \
            _Pragma("unroll")                                                         \
            for (int j = 0; j < 16; j++) {                                            \
                int idx = tid + j * 256;                                              \
                int comp = idx >> 11, rem = idx & 2047;                               \
                int row = rem >> 4, sg = rem & 15;                                    \
                int r = _r0 + 2 * row;                                                \
                int ok = (r >= 0 && r < Lin);                                         \
                const __half* sa = xb + (size_t)comp * planeStride                    \
                    + (size_t)(ok ? r : 0) * CIN + _ci0 + (sg << 3);                  \
                cpa16z(Ab + comp * ACMP + row * ROWB + (sg << 4), sa, ok ? 16u : 0u); \
            }                                                                         \
            _Pragma("unroll")                                                         \
            for (int j = 0; j < 8; j++) {                                             \
                int idx = tid + j * 256;                                              \
                int comp = idx >> 10, rem = idx & 1023;                               \
                int row = rem >> 4, sg = rem & 15;                                    \
                const __half* sbp = ws + (size_t)comp * wcs                           \
                    + ((size_t)(co0 + row) * 10 + _t) * CIN + _ci0 + (sg << 3);       \
                cpa16(Bb + comp * BCMP + row * ROWB + (sg << 4), sbp);                \
            }                                                                         \
            asm volatile("cp.async.commit_group;" ::: "memory");                      \
        } while (0)
        ISSUE_S(0);
        for (int k = 0; k < NC; k++) {
            if (k + 1 < NC) {
                ISSUE_S(k + 1);
                asm volatile("cp.async.wait_group 1;" ::: "memory");
            } else {
                asm volatile("cp.async.wait_group 0;" ::: "memory");
            }
            __syncthreads();
            COMPUTE(k);
        }
    }

    #pragma unroll
    for (int mt = 0; mt < 2; mt++) {
        int lr = l0 + wm * 32 + mt * 16 + (lane >> 2);
        #pragma unroll
        for (int nt = 0; nt < 4; nt++) {
            int col = co0 + wn * 32 + nt * 8 + (lane & 3) * 2;
            float b0 = bias[col], b1 = bias[col + 1];
            if (lr < Lout) {
                float2 v = make_float2(g[mt][nt][0] + b0, g[mt][nt][1] + b1);
                *(float2*)&yT[((size_t)b * Lout + lr) * Cout + col] = v;
            }
            if (lr + 8 < Lout) {
                float2 v = make_float2(g[mt][nt][2] + b0, g[mt][nt][3] + b1);
                *(float2*)&yT[((size_t)b * Lout + lr + 8) * Cout + col] = v;
            }
        }
    }
    #undef COMPUTE
    #undef ISSUE_F
    #undef ISSUE_S
}

// ---------------------------------------------------------------------------
// gemm_mma: out[r][n] = A[r]·B[n] (+bias). Same split scheme (A unscaled
// planes, B x16-scaled planes, 3 products, single fp32 acc, drain x1/16).
// M tile 128, N tile 64, K-chunk 128, NC chunks. Rows/K exact multiples.
// SPLIT: write unscaled fp16 2-plane output (for feats); else fp32.
// ---------------------------------------------------------------------------
template<int NC, bool SPLIT>
__global__ __launch_bounds__(256)
void gemm_mma(const __half* __restrict__ A0, size_t aps,
              const __half* __restrict__ B0, size_t bps,
              const float* __restrict__ bias,
              float* __restrict__ outF, __half* __restrict__ outH, size_t ops,
              int N, int K)
{
    extern __shared__ __align__(128) char smem[];
    uint32_t sbase = smem_u32(smem);
    int tid = threadIdx.x, wid = tid >> 5, lane = tid & 31;
    int wm = wid & 3, wn = wid >> 2;
    int co0 = blockIdx.x * 64;
    int r0  = blockIdx.y * 128;

    float c[2][4][4];
    #pragma unroll
    for (int i = 0; i < 2; i++)
        #pragma unroll
        for (int j = 0; j < 4; j++)
            #pragma unroll
            for (int q = 0; q < 4; q++) c[i][j][q] = 0.0f;

    int row0 = tid >> 4, seg = tid & 15;
    const __half* pA = A0 + (size_t)(r0 + row0) * K + (seg << 3);
    const __half* pB = B0 + (size_t)(co0 + row0) * K + (seg << 3);
    uint32_t smA = (uint32_t)(row0 * ROWB + (seg << 4));
    int fsi = 0;
    #define ISSUE_G() do {                                                            \
        uint32_t Ab = sbase + (uint32_t)(fsi & 1) * BUFB + smA;                       \
        uint32_t Bb = sbase + (uint32_t)(fsi & 1) * BUFB + AHALF + smA;               \
        _Pragma("unroll")                                                             \
        for (int cp = 0; cp < 2; cp++)                                                \
            _Pragma("unroll")                                                         \
            for (int jj = 0; jj < 8; jj++)                                            \
                cpa16(Ab + cp * ACMP + jj * (16 * ROWB),                              \
                      pA + (size_t)cp * aps + (size_t)jj * 16 * K);                   \
        _Pragma("unroll")                                                             \
        for (int cp = 0; cp < 2; cp++)                                                \
            _Pragma("unroll")                                                         \
            for (int jj = 0; jj < 4; jj++)                                            \
                cpa16(Bb + cp * BCMP + jj * (16 * ROWB),                              \
                      pB + (size_t)cp * bps + (size_t)jj * 16 * K);                   \
        asm volatile("cp.async.commit_group;" ::: "memory");                          \
        pA += 128; pB += 128; fsi++;                                                  \
    } while (0)

    ISSUE_G();
    for (int k = 0; k < NC; k++) {
        if (k + 1 < NC) {
            ISSUE_G();
            asm volatile("cp.async.wait_group 1;" ::: "memory");
        } else {
            asm volatile("cp.async.wait_group 0;" ::: "memory");
        }
        __syncthreads();
        uint32_t Ab = sbase + (k & 1) * BUFB;
        uint32_t Bb = Ab + AHALF;
        uint32_t aw = Ab + (wm * 32 + (lane & 15)) * ROWB + (lane >> 4) * 16;
        uint32_t bw = Bb + (wn * 32 + ((lane >> 4) << 3) + (lane & 7)) * ROWB
                        + ((lane >> 3) & 1) * 16;
        #pragma unroll
        for (int ks = 0; ks < 8; ks++) {
            uint32_t a[2][2][4], bf[2][2][4];
            #pragma unroll
            for (int cp = 0; cp < 2; cp++)
                #pragma unroll
                for (int mt = 0; mt < 2; mt++)
                    ldmx4(aw + cp * ACMP + mt * (16 * ROWB) + ks * 32, a[cp][mt]);
            #pragma unroll
            for (int cp = 0; cp < 2; cp++)
                #pragma unroll
                for (int n2 = 0; n2 < 2; n2++)
                    ldmx4(bw + cp * BCMP + n2 * (16 * ROWB) + ks * 32, bf[cp][n2]);
            #pragma unroll
            for (int mt = 0; mt < 2; mt++)
                #pragma unroll
                for (int nt = 0; nt < 4; nt++) {
                    uint32_t b0a = bf[0][nt >> 1][(nt & 1) * 2];
                    uint32_t b0b = bf[0][nt >> 1][(nt & 1) * 2 + 1];
                    uint32_t b1a = bf[1][nt >> 1][(nt & 1) * 2];
                    uint32_t b1b = bf[1][nt >> 1][(nt & 1) * 2 + 1];
                    mma16816(c[mt][nt], a[0][mt], b0a, b0b);
                    mma16816(c[mt][nt], a[0][mt], b1a, b1b);
                    mma16816(c[mt][nt], a[1][mt], b0a, b0b);
                }
        }
        __syncthreads();
    }
    #undef ISSUE_G

    #pragma unroll
    for (int mt = 0; mt < 2; mt++) {
        int lr = r0 + wm * 32 + mt * 16 + (lane >> 2);
        #pragma unroll
        for (int nt = 0; nt < 4; nt++) {
            int col = co0 + wn * 32 + nt * 8 + (lane & 3) * 2;
            float b0 = bias ? bias[col] : 0.0f, b1 = bias ? bias[col + 1] : 0.0f;
            #pragma unroll
            for (int h = 0; h < 2; h++) {
                int rr = lr + 8 * h;
                float v0 = c[mt][nt][2 * h]     * 0.0625f + b0;
                float v1 = c[mt][nt][2 * h + 1] * 0.0625f + b1;
                if (SPLIT) {
                    __half h0 = __float2half(v0), h1 = __float2half(v1);
                    __half r0h = __float2half(v0 - __half2float(h0));
                    __half r1h = __float2half(v1 - __half2float(h1));
                    *(__half2*)&outH[(size_t)rr * N + col] = __halves2half2(h0, h1);
                    *(__half2*)&outH[ops + (size_t)rr * N + col] = __halves2half2(r0h, r1h);
                } else {
                    *(float2*)&outF[(size_t)rr * N + col] = make_float2(v0, v1);
                }
            }
        }
    }
}

// GN stats over [b][l][C]
__global__ __launch_bounds__(256)
void gn_stats_t(const float* __restrict__ x, float* __restrict__ mean,
                float* __restrict__ istd, int L, int C, int G)
{
    int blk = blockIdx.x, b = blk / G, g = blk % G;
    const float* p = x + (size_t)b * L * C + g * 16;
    float s = 0.0f, s2 = 0.0f;
    int tot = L * 16;
    for (int i = threadIdx.x; i < tot; i += 256) {
        int l = i >> 4, cc = i & 15;
        float v = p[(size_t)l * C + cc];
        s += v; s2 = fmaf(v, v, s2);
    }
    __shared__ float sa[256], sbm[256];
    int tid = threadIdx.x;
    sa[tid] = s; sbm[tid] = s2;
    __syncthreads();
    for (int o = 128; o > 0; o >>= 1) {
        if (tid < o) { sa[tid] += sa[tid + o]; sbm[tid] += sbm[tid + o]; }
        __syncthreads();
    }
    if (tid == 0) {
        float m = sa[0] / (float)tot;
        float var = sbm[0] / (float)tot - m * m;
        mean[blk] = m;
        istd[blk] = rsqrtf(var + 1e-5f);
    }
}

// GN apply + GELU + unscaled fp16 2-way split -> planes
__global__ __launch_bounds__(256)
void ng_split(const float* __restrict__ x, const float* __restrict__ mean,
              const float* __restrict__ istd, const float* __restrict__ gma,
              const float* __restrict__ bta, __half* __restrict__ xs,
              size_t ps, int L, int C, int G)
{
    int b = blockIdx.y;
    size_t i4 = (size_t)blockIdx.x * 256 + threadIdx.x;
    size_t n4 = (size_t)L * C >> 2;
    if (i4 >= n4) return;
    size_t base = (size_t)b * L * C;
    float4 v = ((const float4*)(x + base))[i4];
    int cc = (int)((i4 << 2) % (size_t)C);
    int bg = b * G + (cc >> 4);
    float mu = mean[bg], is = istd[bg];
    float o[4] = {v.x, v.y, v.z, v.w};
    __half p0[4], p1[4];
    #pragma unroll
    for (int j = 0; j < 4; j++) {
        float h = gelu_f((o[j] - mu) * is * gma[cc + j] + bta[cc + j]);
        __half a = __float2half(h);
        p0[j] = a;
        p1[j] = __float2half(h - __half2float(a));
    }
    ((uint64_t*)(xs + base))[i4]      = *(uint64_t*)p0;
    ((uint64_t*)(xs + ps + base))[i4] = *(uint64_t*)p1;
}

__global__ __launch_bounds__(256)
void cb_norms(const float* __restrict__ cbk, float* __restrict__ cn)
{
    const float4* row = (const float4*)(cbk + (size_t)blockIdx.x * 1536);
    float s = 0.0f;
    for (int i = threadIdx.x; i < 384; i += 256) {
        float4 v = row[i];
        s += v.x * v.x + v.y * v.y + v.z * v.z + v.w * v.w;
    }
    __shared__ float sa[256];
    int tid = threadIdx.x;
    sa[tid] = s;
    __syncthreads();
    for (int o = 128; o > 0; o >>= 1) {
        if (tid < o) sa[tid] += sa[tid + o];
        __syncthreads();
    }
    if (tid == 0) cn[blockIdx.x] = sa[0];
}

__global__ __launch_bounds__(256)
void vq_argmin(const float* __restrict__ sc, const float* __restrict__ cn,
               int* __restrict__ idx, int NS)
{
    int g = blockIdx.x * 8 + (threadIdx.x >> 5);
    int lane = threadIdx.x & 31;
    if (g >= NS) return;
    const float* s = sc + (size_t)g * 1024;
    float best = 3.4e38f; int bi = 1 << 30;
    for (int j = lane; j < 1024; j += 32) {
        float d = fmaf(-2.0f, s[j], cn[j]);
        if (d < best) { best = d; bi = j; }
    }
    #pragma unroll
    for (int o = 16; o > 0; o >>= 1) {
        float ov = __shfl_xor_sync(0xffffffffu, best, o);
        int   oi = __shfl_xor_sync(0xffffffffu, bi,   o);
        if (ov < best || (ov == best && oi < bi)) { best = ov; bi = oi; }
    }
    if (lane == 0) idx[g] = bi;
}

__global__ __launch_bounds__(256)
void final_ln(const float* __restrict__ cbk, const int* __restrict__ idx,
              const float* __restrict__ pos, const float* __restrict__ mod,
              const float* __restrict__ lng, const float* __restrict__ lnb,
              float* __restrict__ out, int S, int NS)
{
    int n = blockIdx.x, s = n % S, tid = threadIdx.x;
    __shared__ float row[1536];
    __shared__ float sa[256], sbm[256];
    const float* c = cbk + (size_t)idx[n] * 1536;
    const float* p = pos + (size_t)s * 1536;
    float ls = 0.0f, ls2 = 0.0f;
    for (int e = tid; e < 1536; e += 256) {
        float v = c[e] + p[e] + mod[e];
        row[e] = v;
        ls += v; ls2 = fmaf(v, v, ls2);
    }
    sa[tid] = ls; sbm[tid] = ls2;
    __syncthreads();
    for (int o = 128; o > 0; o >>= 1) {
        if (tid < o) { sa[tid] += sa[tid + o]; sbm[tid] += sbm[tid + o]; }
        __syncthreads();
    }
    float m = sa[0] * (1.0f / 1536.0f);
    float var = sbm[0] * (1.0f / 1536.0f) - m * m;
    float r = rsqrtf(var + 1e-5f);
    for (int e = tid; e < 1536; e += 256)
        out[(size_t)n * 1536 + e] = (row[e] - m) * r * lng[e] + lnb[e];
    if (tid == 0) {
        out[(size_t)NS * 1536 + n]      = 1.0f;
        out[(size_t)NS * 1536 + NS + n] = (float)idx[n];
    }
}

extern "C" void kernel_launch(void* const* d_in, const int* in_sizes, int n_in,
                              void* d_out, int out_size)
{
    const float* wav = (const float*)d_in[0];
    const float* w0  = (const float*)d_in[1];
    const float* b0  = (const float*)d_in[2];
    const float* w1  = (const float*)d_in[3];
    const float* b1  = (const float*)d_in[4];
    const float* wr  = (const float*)d_in[5];
    const float* br  = (const float*)d_in[6];
    const float* g0  = (const float*)d_in[7];
    const float* bb0 = (const float*)d_in[8];
    const float* gr  = (const float*)d_in[9];
    const float* brr = (const float*)d_in[10];
    const float* pw  = (const float*)d_in[11];
    const float* pb  = (const float*)d_in[12];
    const float* cbk = (const float*)d_in[13];
    const float* pos = (const float*)d_in[14];
    const float* mod = (const float*)d_in[15];
    const float* lng = (const float*)d_in[16];
    const float* lnb = (const float*)d_in[17];
    float* out = (float*)d_out;

    const int B = 8;
    int Lw = in_sizes[0] / B;
    int L[7];
    L[0] = Lw / 5 + 1;
    for (int i = 1; i <= 6; i++) L[i] = L[i - 1] / 2 + 1;

    float *bufA, *bufB, *mean_, *istd_, *cn_;
    __half *xt_, *ws_;
    int *idx_;
    cudaGetSymbolAddress((void**)&bufA,  g_bufA);
    cudaGetSymbolAddress((void**)&bufB,  g_bufB);
    cudaGetSymbolAddress((void**)&xt_,   g_xt);
    cudaGetSymbolAddress((void**)&ws_,   g_ws);
    cudaGetSymbolAddress((void**)&mean_, g_mean);
    cudaGetSymbolAddress((void**)&istd_, g_istd);
    cudaGetSymbolAddress((void**)&cn_,   g_cnorm);
    cudaGetSymbolAddress((void**)&idx_,  g_idx);

    const int SMEMSZ = NSTG * BUFB;   // 208896
    cudaFuncSetAttribute(conv_mma<256>, cudaFuncAttributeMaxDynamicSharedMemorySize, SMEMSZ);
    cudaFuncSetAttribute(conv_mma<512>, cudaFuncAttributeMaxDynamicSharedMemorySize, SMEMSZ);
    cudaFuncSetAttribute(gemm_mma<4, true>,   cudaFuncAttributeMaxDynamicSharedMemorySize, SMEMSZ);
    cudaFuncSetAttribute(gemm_mma<12, false>, cudaFuncAttributeMaxDynamicSharedMemorySize, SMEMSZ);

    // split-weight planes for tail GEMMs (in g_ws tail space)
    __half* wsP = ws_ + 28835840;                 // pw planes: 2 x 786432
    __half* cbP = wsP + 2 * 786432;               // cbk planes: 2 x 1572864

    cb_norms<<<1024, 256>>>(cbk, cn_);
    wprep_all<<<dim3(512, 6), 256>>>(w1, wr, ws_);
    msplit<<<1536, 256>>>(pw, wsP, 512);
    msplit<<<1024, 256>>>(cbk, cbP, 1536);

    conv0_t<<<dim3((L[0] + 15) / 16, B), 256>>>(wav, w0, b0, bufA, Lw, L[0]);
    gn_stats_t<<<B * 16, 256>>>(bufA, mean_, istd_, L[0], 256, 16);
    {
        size_t ps = (size_t)B * L[0] * 256;
        int nb = (int)(((size_t)L[0] * 256 / 4 + 255) / 256);
        ng_split<<<dim3(nb, B), 256>>>(bufA, mean_, istd_, g0, bb0, xt_, ps, L[0], 256, 16);
    }

    // layer 1 (MMA, Cin=256)
    conv_mma<256><<<dim3(8, (L[1] + 127) / 128, B), 256, SMEMSZ>>>(
        xt_, (size_t)B * L[0] * 256, ws_, 1310720, b1, bufA, 512, L[0], L[1]);
    gn_stats_t<<<B * 32, 256>>>(bufA, mean_, istd_, L[1], 512, 32);
    {
        size_t ps = (size_t)B * L[1] * 512;
        int nb = (int)(((size_t)L[1] * 512 / 4 + 255) / 256);
        ng_split<<<dim3(nb, B), 256>>>(bufA, mean_, istd_, gr, brr, xt_, ps, L[1], 512, 32);
    }

    // layers 2..6 (MMA, Cin=512); last layer splits y6 into planes too
    for (int i = 0; i < 5; i++) {
        int Lin = L[1 + i], Lo = L[2 + i];
        conv_mma<512><<<dim3(8, (Lo + 127) / 128, B), 256, SMEMSZ>>>(
            xt_, (size_t)B * Lin * 512, ws_ + 2621440 + (size_t)i * 5242880, 2621440,
            br + i * 512, bufA, 512, Lin, Lo);
        gn_stats_t<<<B * 32, 256>>>(bufA, mean_, istd_, Lo, 512, 32);
        int nb = (int)(((size_t)Lo * 512 / 4 + 255) / 256);
        size_t ps = (size_t)B * Lo * 512;
        ng_split<<<dim3(nb, B), 256>>>(bufA, mean_, istd_, gr + (i + 1) * 512,
                                       brr + (i + 1) * 512, xt_, ps, Lo, 512, 32);
    }

    int S = L[6];           // 976
    int NS = B * S;         // 7808 = 61 * 128

    // projection on tensor cores: feats planes (fp16 x2) from y6 planes x pw planes
    size_t psY = (size_t)NS * 512;                // y6 plane stride
    __half* featP = xt_ + 2 * psY;                // feat planes after y6 planes
    size_t psF = (size_t)NS * 1536;
    gemm_mma<4, true><<<dim3(24, NS / 128), 256, SMEMSZ>>>(
        xt_, psY, wsP, 786432, pb, nullptr, featP, psF, 1536, 512);

    // VQ scores on tensor cores -> bufB
    gemm_mma<12, false><<<dim3(16, NS / 128), 256, SMEMSZ>>>(
        featP, psF, cbP, 1572864, nullptr, bufB, nullptr, 0, 1024, 1536);

    vq_argmin<<<(NS + 7) / 8, 256>>>(bufB, cn_, idx_, NS);
    final_ln<<<NS, 256>>>(cbk, idx_, pos, mod, lng, lnb, out, S, NS);
}